// round 6
// baseline (speedup 1.0000x reference)
#include <cuda_runtime.h>
#include <cuda_pipeline_primitives.h>
#include <stdint.h>

#define NF            4096
#define ROWS_PER_BLK  8
#define TILE          512            // floats per row per stage
#define NT            8              // tiles per row (NF/TILE)
#define THREADS       256
#define GRID          512            // persistent: <= 4/SM capacity (592)

__device__ float g_v[NF];

// ---------------------------------------------------------------------------
// Kernel A: build folded coefficient vector
//   v[f] = sum_i [flat_idx[i]==f] * w_flat[i] * diag_w[seg_ids[i]] * dense_W[seg_ids[i]]
// Triggers programmatic launch completion at entry so the dependent GEMV can
// start its x-prefetch while this runs.
// ---------------------------------------------------------------------------
__global__ void __launch_bounds__(1024)
build_coef_kernel(const void* __restrict__ flat_idx_raw,
                  const void* __restrict__ seg_ids_raw,
                  const float* __restrict__ w_flat,
                  const float* __restrict__ diag_w,
                  const float* __restrict__ dense_W,
                  int total) {
    cudaTriggerProgrammaticLaunchCompletion();

    __shared__ float sv[NF];
    __shared__ float gsc[1024];      // per-group diag_w * dense_W
    const int tid = threadIdx.x;

    for (int i = tid; i < NF; i += 1024) sv[i] = 0.0f;
    gsc[tid] = diag_w[tid] * dense_W[tid];

    // int32-vs-int64 index dtype detection (idx<4096 -> int64 high words all 0).
    const int* probe = (const int*)flat_idx_raw;
    int is64 = 1;
    #pragma unroll
    for (int k = 0; k < 16; k++) is64 &= (probe[2 * k + 1] == 0);

    __syncthreads();

    const int*       fi32 = (const int*)flat_idx_raw;
    const long long* fi64 = (const long long*)flat_idx_raw;
    const int*       sg32 = (const int*)seg_ids_raw;
    const long long* sg64 = (const long long*)seg_ids_raw;

    #pragma unroll 5
    for (int i = tid; i < total; i += 1024) {
        int f = is64 ? (int)fi64[i] : fi32[i];
        int g = is64 ? (int)sg64[i] : sg32[i];
        atomicAdd(&sv[f], w_flat[i] * gsc[g]);
    }
    __syncthreads();

    for (int i = tid; i < NF; i += 1024) g_v[i] = sv[i];
}

// ---------------------------------------------------------------------------
// Kernel B: persistent GEMV.  512 blocks (one wave), each handles
// n_groups/512 row-groups of 8 rows (one per warp).  The cp.async double
// buffer is carried FLAT across group boundaries: one pipeline ramp and one
// drain per block instead of per group -> no wave quantization, minimal
// drain bubbles.
// ---------------------------------------------------------------------------
__global__ void __launch_bounds__(THREADS, 4)
gemv_kernel(const float* __restrict__ x,
            float* __restrict__ out,
            int batch) {
    __shared__ __align__(16) float sv[NF];                       // 16 KB
    __shared__ __align__(16) float sx[2][ROWS_PER_BLK][TILE];    // 32 KB

    const int tid  = threadIdx.x;
    const int w    = tid >> 5;
    const int lane = tid & 31;
    const int bid  = blockIdx.x;
    const int grid = gridDim.x;

    const int n_groups  = (batch + ROWS_PER_BLK - 1) / ROWS_PER_BLK;
    const int my_groups = (n_groups - bid + grid - 1) / grid;  // groups for this block
    const int tot_tiles = my_groups * NT;

    // Row (clamped) for flat tile index i of this block's work list.
    auto row_of = [&](int i) -> int {
        int g = bid + (i >> 3) * grid;
        int r = g * ROWS_PER_BLK + w;
        return r < batch ? r : batch - 1;
    };

    // Prefetch the first two tiles before the PDL sync (independent of g_v).
    #pragma unroll
    for (int s = 0; s < 2; s++) {
        if (s < tot_tiles) {
            const float* src = x + (size_t)row_of(s) * NF + (s & 7) * TILE;
            #pragma unroll
            for (int j = 0; j < 4; j++) {
                const int c = (lane + 32 * j) * 4;
                __pipeline_memcpy_async(&sx[s][w][c], src + c, 16);
            }
            __pipeline_commit();
        }
    }

    // Wait for build_coef_kernel (g_v ready).
    cudaGridDependencySynchronize();

    // Copy v into shared while prefetches are in flight.
    {
        const float4* __restrict__ gv  = (const float4*)g_v;
        float4*       __restrict__ svv = (float4*)sv;
        #pragma unroll
        for (int i = 0; i < (NF / 4) / THREADS; i++)
            svv[tid + i * THREADS] = gv[tid + i * THREADS];
    }
    __syncthreads();

    float acc = 0.0f;

    for (int i = 0; i < tot_tiles; i++) {
        if (i < tot_tiles - 1) __pipeline_wait_prior(1);
        else                   __pipeline_wait_prior(0);

        const int t = i & 7;
        const float4* __restrict__ xs = (const float4*)sx[i & 1][w];
        const float4* __restrict__ vs = (const float4*)(sv + t * TILE);

        // Registers first...
        float4 xa = xs[lane +  0], va = vs[lane +  0];
        float4 xb = xs[lane + 32], vb = vs[lane + 32];
        float4 xc = xs[lane + 64], vc = vs[lane + 64];
        float4 xd = xs[lane + 96], vd = vs[lane + 96];

        // ...refill the consumed buffer with tile i+2 (thread-local WAR safe)...
        if (i + 2 < tot_tiles) {
            const int ni = i + 2;
            const float* src = x + (size_t)row_of(ni) * NF + (ni & 7) * TILE;
            #pragma unroll
            for (int j = 0; j < 4; j++) {
                const int c = (lane + 32 * j) * 4;
                __pipeline_memcpy_async(&sx[i & 1][w][c], src + c, 16);
            }
            __pipeline_commit();
        }

        // ...then compute.
        float a0 = xa.x * va.x + xa.y * va.y + xa.z * va.z + xa.w * va.w;
        float a1 = xb.x * vb.x + xb.y * vb.y + xb.z * vb.z + xb.w * vb.w;
        float a2 = xc.x * vc.x + xc.y * vc.y + xc.z * vc.z + xc.w * vc.w;
        float a3 = xd.x * vd.x + xd.y * vd.y + xd.z * vd.z + xd.w * vd.w;
        acc += (a0 + a1) + (a2 + a3);

        // End of a row: reduce and emit.
        if (t == 7) {
            #pragma unroll
            for (int o = 16; o; o >>= 1)
                acc += __shfl_xor_sync(0xffffffffu, acc, o);
            int g   = bid + (i >> 3) * grid;
            int r   = g * ROWS_PER_BLK + w;
            if (lane == 0 && r < batch) out[r] = acc;
            acc = 0.0f;
        }
    }
}

// Inputs (metadata order): x [B*4096] f32, flat_idx [total], seg_ids [total],
// w_flat [total] f32, diag_w [1024] f32, dense_W [1024] f32. Output: [B] f32.
extern "C" void kernel_launch(void* const* d_in, const int* in_sizes, int n_in,
                              void* d_out, int out_size) {
    const float* x       = (const float*)d_in[0];
    const void*  flatidx = d_in[1];
    const void*  segids  = d_in[2];
    const float* w_flat  = (const float*)d_in[3];
    const float* diag_w  = (const float*)d_in[4];
    const float* dense_W = (const float*)d_in[5];

    int total = in_sizes[1];
    int batch = in_sizes[0] / NF;

    build_coef_kernel<<<1, 1024>>>(flatidx, segids, w_flat, diag_w, dense_W,
                                   total);

    int n_groups = (batch + ROWS_PER_BLK - 1) / ROWS_PER_BLK;
    int blocks = n_groups < GRID ? n_groups : GRID;
    float* outp = (float*)d_out;

    cudaLaunchConfig_t cfg = {};
    cfg.gridDim  = dim3(blocks, 1, 1);
    cfg.blockDim = dim3(THREADS, 1, 1);
    cfg.dynamicSmemBytes = 0;
    cfg.stream = 0;

    cudaLaunchAttribute attr;
    attr.id = cudaLaunchAttributeProgrammaticStreamSerialization;
    attr.val.programmaticStreamSerializationAllowed = 1;
    cfg.attrs = &attr;
    cfg.numAttrs = 1;

    cudaLaunchKernelEx(&cfg, gemv_kernel, x, outp, batch);
}

// round 7
// speedup vs baseline: 1.0010x; 1.0010x over previous
#include <cuda_runtime.h>
#include <cuda_pipeline_primitives.h>
#include <stdint.h>

#define NF        4096
#define WARPS     8
#define WSLICE    512               // floats per warp column-slice (NF/WARPS)
#define THREADS   256
#define STAGES    3                 // 3 x 16KB row buffers = 48KB static smem
#define GRID      592               // 4 blocks x 148 SMs, exact fill

__device__ float g_v[NF];

// ---------------------------------------------------------------------------
// Kernel A: build folded coefficient vector
//   v[f] = sum_i [flat_idx[i]==f] * w_flat[i] * diag_w[seg_ids[i]] * dense_W[seg_ids[i]]
// Fires programmatic launch completion at entry so the GEMV can begin its
// x-prefetch concurrently.
// ---------------------------------------------------------------------------
__global__ void __launch_bounds__(1024)
build_coef_kernel(const void* __restrict__ flat_idx_raw,
                  const void* __restrict__ seg_ids_raw,
                  const float* __restrict__ w_flat,
                  const float* __restrict__ diag_w,
                  const float* __restrict__ dense_W,
                  int total) {
    cudaTriggerProgrammaticLaunchCompletion();

    __shared__ float sv[NF];
    __shared__ float gsc[1024];
    const int tid = threadIdx.x;

    for (int i = tid; i < NF; i += 1024) sv[i] = 0.0f;
    gsc[tid] = diag_w[tid] * dense_W[tid];

    // int32-vs-int64 index dtype detection (idx<4096 -> int64 high words all 0).
    const int* probe = (const int*)flat_idx_raw;
    int is64 = 1;
    #pragma unroll
    for (int k = 0; k < 16; k++) is64 &= (probe[2 * k + 1] == 0);

    __syncthreads();

    const int*       fi32 = (const int*)flat_idx_raw;
    const long long* fi64 = (const long long*)flat_idx_raw;
    const int*       sg32 = (const int*)seg_ids_raw;
    const long long* sg64 = (const long long*)seg_ids_raw;

    #pragma unroll 5
    for (int i = tid; i < total; i += 1024) {
        int f = is64 ? (int)fi64[i] : fi32[i];
        int g = is64 ? (int)sg64[i] : sg32[i];
        atomicAdd(&sv[f], w_flat[i] * gsc[g]);
    }
    __syncthreads();

    for (int i = tid; i < NF; i += 1024) g_v[i] = sv[i];
}

// ---------------------------------------------------------------------------
// Kernel B: persistent GEMV, warp-per-column-slice.
//  - Block b owns a contiguous row range; processes ONE row per pipeline
//    stage (16KB contiguous DRAM reads -> sequential per-block streams).
//  - Warp w owns columns [512w, 512w+512); its v-slice lives in 16 registers
//    per lane (no sv in shared, no v LDS traffic).
//  - 3-stage cp.async ring (48KB). Per row: warp shuffle-reduce then one
//    float atomicAdd into out[row] (row is block-exclusive; zeroed upfront).
// ---------------------------------------------------------------------------
__global__ void __launch_bounds__(THREADS, 4)
gemv_kernel(const float* __restrict__ x,
            float* __restrict__ out,
            int batch) {
    __shared__ __align__(16) float sx[STAGES][NF];   // 3 x 16KB = 48KB

    const int tid  = threadIdx.x;
    const int w    = tid >> 5;
    const int lane = tid & 31;
    const int bid  = blockIdx.x;
    const int grid = gridDim.x;

    // Contiguous row partition: base rows + 1 extra for the first `rem` blocks.
    const int base  = batch / grid;
    const int rem   = batch - base * grid;
    const int cnt   = base + (bid < rem);
    const int start = bid * base + (bid < rem ? bid : rem);

    // Byte/chunk offsets this thread copies & reads: float4 index l + 32j
    // within the warp's 2KB slice.
    const int woff = w * WSLICE;     // float offset of warp slice within a row

    // ---- Prefetch first 3 rows (independent of g_v -> before PDL sync) ----
    #pragma unroll
    for (int s = 0; s < STAGES; s++) {
        if (s < cnt) {
            const float* src = x + (size_t)(start + s) * NF + woff;
            #pragma unroll
            for (int j = 0; j < 4; j++) {
                const int c = (lane + 32 * j) * 4;
                __pipeline_memcpy_async(&sx[s][woff + c], src + c, 16);
            }
        }
        __pipeline_commit();
    }

    // Zero this block's output rows (poisoned by harness).
    for (int r = tid; r < cnt; r += THREADS) out[start + r] = 0.0f;

    // Wait for build_coef_kernel (g_v ready).
    cudaGridDependencySynchronize();

    // Load this lane's v-slice into registers: 4 float4.
    const float4* __restrict__ gv4 = (const float4*)(g_v + woff);
    float4 v0 = __ldg(&gv4[lane +  0]);
    float4 v1 = __ldg(&gv4[lane + 32]);
    float4 v2 = __ldg(&gv4[lane + 64]);
    float4 v3 = __ldg(&gv4[lane + 96]);

    // Make the zeroed out[] visible to all warps before any atomicAdd.
    __syncthreads();

    // ---- Main loop: one row per iteration ----
    for (int i = 0; i < cnt; i++) {
        __pipeline_wait_prior(STAGES - 1);   // row i landed

        const int s = i % STAGES;
        const float4* __restrict__ xs = (const float4*)(sx[s] + woff);

        float4 xa = xs[lane +  0];
        float4 xb = xs[lane + 32];
        float4 xc = xs[lane + 64];
        float4 xd = xs[lane + 96];

        // Refill this stage with row i+STAGES (thread-local WAR safe).
        if (i + STAGES < cnt) {
            const float* src = x + (size_t)(start + i + STAGES) * NF + woff;
            #pragma unroll
            for (int j = 0; j < 4; j++) {
                const int c = (lane + 32 * j) * 4;
                __pipeline_memcpy_async(&sx[s][woff + c], src + c, 16);
            }
        }
        __pipeline_commit();

        float a0 = xa.x * v0.x + xa.y * v0.y + xa.z * v0.z + xa.w * v0.w;
        float a1 = xb.x * v1.x + xb.y * v1.y + xb.z * v1.z + xb.w * v1.w;
        float a2 = xc.x * v2.x + xc.y * v2.y + xc.z * v2.z + xc.w * v2.w;
        float a3 = xd.x * v3.x + xd.y * v3.y + xd.z * v3.z + xd.w * v3.w;
        float acc = (a0 + a1) + (a2 + a3);

        #pragma unroll
        for (int o = 16; o; o >>= 1)
            acc += __shfl_xor_sync(0xffffffffu, acc, o);

        if (lane == 0) atomicAdd(&out[start + i], acc);
    }
}

// Inputs (metadata order): x [B*4096] f32, flat_idx [total], seg_ids [total],
// w_flat [total] f32, diag_w [1024] f32, dense_W [1024] f32. Output: [B] f32.
extern "C" void kernel_launch(void* const* d_in, const int* in_sizes, int n_in,
                              void* d_out, int out_size) {
    const float* x       = (const float*)d_in[0];
    const void*  flatidx = d_in[1];
    const void*  segids  = d_in[2];
    const float* w_flat  = (const float*)d_in[3];
    const float* diag_w  = (const float*)d_in[4];
    const float* dense_W = (const float*)d_in[5];

    int total = in_sizes[1];
    int batch = in_sizes[0] / NF;

    build_coef_kernel<<<1, 1024>>>(flatidx, segids, w_flat, diag_w, dense_W,
                                   total);

    int blocks = batch < GRID ? batch : GRID;
    float* outp = (float*)d_out;

    cudaLaunchConfig_t cfg = {};
    cfg.gridDim  = dim3(blocks, 1, 1);
    cfg.blockDim = dim3(THREADS, 1, 1);
    cfg.dynamicSmemBytes = 0;
    cfg.stream = 0;

    cudaLaunchAttribute attr;
    attr.id = cudaLaunchAttributeProgrammaticStreamSerialization;
    attr.val.programmaticStreamSerializationAllowed = 1;
    cfg.attrs = &attr;
    cfg.numAttrs = 1;

    cudaLaunchKernelEx(&cfg, gemv_kernel, x, outp, batch);
}

// round 8
// speedup vs baseline: 1.0609x; 1.0598x over previous
#include <cuda_runtime.h>
#include <cuda_pipeline_primitives.h>
#include <stdint.h>

#define NF        4096
#define WSLICE    512               // floats per warp column-slice (NF/8)
#define THREADS   256
#define STAGES    6                 // 6 x 16KB row buffers = 96KB dynamic smem
#define GRID      296               // 2 blocks x 148 SMs, exact fill

__device__ float g_v[NF];

// ---------------------------------------------------------------------------
// Kernel A: build folded coefficient vector
//   v[f] = sum_i [flat_idx[i]==f] * w_flat[i] * diag_w[seg_ids[i]] * dense_W[seg_ids[i]]
// Latency-optimized: PDL trigger at entry; all item loads batched (MLP ~15)
// via predicated unroll; index dtype handled by low-word addressing
// (values < 2^31, little-endian -> fi32[i << is64] is correct for both).
// ---------------------------------------------------------------------------
__global__ void __launch_bounds__(1024)
build_coef_kernel(const void* __restrict__ flat_idx_raw,
                  const void* __restrict__ seg_ids_raw,
                  const float* __restrict__ w_flat,
                  const float* __restrict__ diag_w,
                  const float* __restrict__ dense_W,
                  int total) {
    cudaTriggerProgrammaticLaunchCompletion();

    __shared__ float sv[NF];
    const int tid = threadIdx.x;

    // is64 probe (L1-hot after lane 0 of first warp).
    const int* probe = (const int*)flat_idx_raw;
    int is64 = 1;
    #pragma unroll
    for (int k = 0; k < 16; k++) is64 &= (probe[2 * k + 1] == 0);

    for (int i = tid; i < NF; i += 1024) sv[i] = 0.0f;

    const int* fi32 = (const int*)flat_idx_raw;
    const int* sg32 = (const int*)seg_ids_raw;

    // Batch all loads first: up to 5 items/thread (total <= 5120 expected).
    int   f[5], g[5];
    float wf[5];
    #pragma unroll
    for (int k = 0; k < 5; k++) {
        int i = tid + k * 1024;
        bool p = i < total;
        f[k]  = p ? fi32[i << is64] : 0;
        g[k]  = p ? sg32[i << is64] : 0;
        wf[k] = p ? w_flat[i]       : 0.0f;
    }
    // Parallel dependent scale loads.
    float c[5];
    #pragma unroll
    for (int k = 0; k < 5; k++)
        c[k] = wf[k] * __ldg(&diag_w[g[k]]) * __ldg(&dense_W[g[k]]);

    __syncthreads();  // sv zeroed

    #pragma unroll
    for (int k = 0; k < 5; k++)
        if (tid + k * 1024 < total) atomicAdd(&sv[f[k]], c[k]);

    // Robustness tail if total > 5120 (not expected for this dataset).
    for (int i = tid + 5120; i < total; i += 1024) {
        int ff = fi32[i << is64], gg = sg32[i << is64];
        atomicAdd(&sv[ff], w_flat[i] * diag_w[gg] * dense_W[gg]);
    }
    __syncthreads();

    for (int i = tid; i < NF; i += 1024) g_v[i] = sv[i];
}

// ---------------------------------------------------------------------------
// Kernel B: persistent GEMV, warp-per-column-slice, 6-deep cp.async ring in
// 96KB dynamic smem (2 blocks/SM, grid=296).  Block owns a contiguous row
// range (~28 rows = 448KB sequential DRAM stream).  v-slice in registers.
// ---------------------------------------------------------------------------
__global__ void __launch_bounds__(THREADS, 2)
gemv_kernel(const float* __restrict__ x,
            float* __restrict__ out,
            int batch) {
    extern __shared__ __align__(16) float sx[];   // STAGES * NF floats

    const int tid  = threadIdx.x;
    const int w    = tid >> 5;
    const int lane = tid & 31;
    const int bid  = blockIdx.x;
    const int grid = gridDim.x;

    const int base  = batch / grid;
    const int rem   = batch - base * grid;
    const int cnt   = base + (bid < rem);
    const int start = bid * base + (bid < rem ? bid : rem);

    const int woff = w * WSLICE;

    // ---- Prefetch first STAGES rows (independent of g_v -> before PDL sync)
    #pragma unroll
    for (int s = 0; s < STAGES; s++) {
        if (s < cnt) {
            const float* src = x + (size_t)(start + s) * NF + woff;
            float* dst = sx + s * NF + woff;
            #pragma unroll
            for (int j = 0; j < 4; j++) {
                const int c = (lane + 32 * j) * 4;
                __pipeline_memcpy_async(dst + c, src + c, 16);
            }
        }
        __pipeline_commit();   // always: one group per row slot
    }

    // Zero this block's output rows (poisoned by harness); independent of g_v.
    for (int r = tid; r < cnt; r += THREADS) out[start + r] = 0.0f;

    // Wait for build_coef_kernel (g_v ready).
    cudaGridDependencySynchronize();

    // This lane's v-slice: 4 float4 in registers.
    const float4* __restrict__ gv4 = (const float4*)(g_v + woff);
    float4 v0 = __ldg(&gv4[lane +  0]);
    float4 v1 = __ldg(&gv4[lane + 32]);
    float4 v2 = __ldg(&gv4[lane + 64]);
    float4 v3 = __ldg(&gv4[lane + 96]);

    __syncthreads();  // out[] zeroing visible before atomics

    // ---- Main loop: one row per iteration, 6-deep ring ----
    for (int i = 0; i < cnt; i++) {
        __pipeline_wait_prior(STAGES - 1);   // row i landed (this thread's part)

        const int s = i % STAGES;
        const float4* __restrict__ xs = (const float4*)(sx + s * NF + woff);

        float4 xa = xs[lane +  0];
        float4 xb = xs[lane + 32];
        float4 xc = xs[lane + 64];
        float4 xd = xs[lane + 96];

        // Refill this slot with row i+STAGES (thread-local WAR safe).
        if (i + STAGES < cnt) {
            const float* src = x + (size_t)(start + i + STAGES) * NF + woff;
            float* dst = sx + s * NF + woff;
            #pragma unroll
            for (int j = 0; j < 4; j++) {
                const int c = (lane + 32 * j) * 4;
                __pipeline_memcpy_async(dst + c, src + c, 16);
            }
        }
        __pipeline_commit();

        float a0 = xa.x * v0.x + xa.y * v0.y + xa.z * v0.z + xa.w * v0.w;
        float a1 = xb.x * v1.x + xb.y * v1.y + xb.z * v1.z + xb.w * v1.w;
        float a2 = xc.x * v2.x + xc.y * v2.y + xc.z * v2.z + xc.w * v2.w;
        float a3 = xd.x * v3.x + xd.y * v3.y + xd.z * v3.z + xd.w * v3.w;
        float acc = (a0 + a1) + (a2 + a3);

        #pragma unroll
        for (int o = 16; o; o >>= 1)
            acc += __shfl_xor_sync(0xffffffffu, acc, o);

        if (lane == 0) atomicAdd(&out[start + i], acc);  // RED, no return
    }
}

// Inputs (metadata order): x [B*4096] f32, flat_idx [total], seg_ids [total],
// w_flat [total] f32, diag_w [1024] f32, dense_W [1024] f32. Output: [B] f32.
extern "C" void kernel_launch(void* const* d_in, const int* in_sizes, int n_in,
                              void* d_out, int out_size) {
    const float* x       = (const float*)d_in[0];
    const void*  flatidx = d_in[1];
    const void*  segids  = d_in[2];
    const float* w_flat  = (const float*)d_in[3];
    const float* diag_w  = (const float*)d_in[4];
    const float* dense_W = (const float*)d_in[5];

    int total = in_sizes[1];
    int batch = in_sizes[0] / NF;

    const int smem_bytes = STAGES * NF * sizeof(float);   // 96 KB
    static bool attr_set = false;
    if (!attr_set) {
        cudaFuncSetAttribute(gemv_kernel,
                             cudaFuncAttributeMaxDynamicSharedMemorySize,
                             smem_bytes);
        attr_set = true;
    }

    build_coef_kernel<<<1, 1024>>>(flatidx, segids, w_flat, diag_w, dense_W,
                                   total);

    int blocks = batch < GRID ? batch : GRID;
    float* outp = (float*)d_out;

    cudaLaunchConfig_t cfg = {};
    cfg.gridDim  = dim3(blocks, 1, 1);
    cfg.blockDim = dim3(THREADS, 1, 1);
    cfg.dynamicSmemBytes = smem_bytes;
    cfg.stream = 0;

    cudaLaunchAttribute attr;
    attr.id = cudaLaunchAttributeProgrammaticStreamSerialization;
    attr.val.programmaticStreamSerializationAllowed = 1;
    cfg.attrs = &attr;
    cfg.numAttrs = 1;

    cudaLaunchKernelEx(&cfg, gemv_kernel, x, outp, batch);
}